// round 16
// baseline (speedup 1.0000x reference)
#include <cuda_runtime.h>
#include <float.h>

// ROI adaptive max pool 7x7 — R15 (warp-private, barrier-free) + one-bin-
// ahead first-row prefetch: bin i+1's first load is issued before bin i's
// reduction, hiding the per-bin dependent-load latency.
// images: [8,256,56,56] f32; rois: [256,4] f32; roi_idx: [256] i32
// out: [256,256,7,7] f32

#define Hc 56
#define Wc 56
#define Cc 256
#define Rc 256
#define OUTN 7
#define CPB 16
#define W4 (Wc / 4)   // 14

__device__ __forceinline__ float4 fm4(float4 a, float4 b) {
    return make_float4(fmaxf(a.x, b.x), fmaxf(a.y, b.y),
                       fmaxf(a.z, b.z), fmaxf(a.w, b.w));
}

__global__ __launch_bounds__(256, 7) void roipool_kernel(
    const float* __restrict__ images,
    const float* __restrict__ rois,
    const int* __restrict__ roi_idx,
    float* __restrict__ out)
{
    __shared__ float rowp[CPB][OUTN][60];

    const int r  = blockIdx.y;
    const int cg = blockIdx.x;
    const int tx = threadIdx.x;            // 0..15 quad
    const int ty = threadIdx.y;            // 0..15 channel
    const int lane = (ty & 1) * 16 + tx;   // lane within warp

    const float4 rv = ((const float4*)rois)[r];
    const int x1 = (int)floorf(rv.x * (float)Wc);
    const int y1 = (int)floorf(rv.y * (float)Hc);
    const int x2 = (int)ceilf (rv.z * (float)Wc);
    const int y2 = (int)ceilf (rv.w * (float)Hc);
    const int Hr = y2 - y1;
    const int Wr = x2 - x1;

    const int n_img = roi_idx[r];
    const float* __restrict__ img =
        images + (size_t)(n_img * Cc + cg * CPB + ty) * (Hc * Wc);

    // ---- Phase 1: row-bin maxes with one-bin-ahead prefetch ----
    const int qlo = x1 >> 2;
    const int qhi = (x2 + 3) >> 2;
    if (tx >= qlo && tx < qhi) {
        const float4* __restrict__ base = (const float4*)img + tx;

        // bin starts (registers, fully unrolled)
        int sArr[OUTN + 1];
        #pragma unroll
        for (int i = 0; i <= OUTN; i++)
            sArr[i] = y1 + (i * Hr) / OUTN;   // sArr[7] used only as dummy

        // prefetch bin 0's first row
        float4 nx = base[sArr[0] * W4];

        #pragma unroll
        for (int i = 0; i < OUTN; i++) {
            const int s = sArr[i];
            const int n = (y1 + ((i + 1) * Hr + OUTN - 1) / OUTN) - s;  // >=1
            const float4* __restrict__ p = base + s * W4;
            float4 m = nx;                      // first row, already in flight
            // prefetch next bin's first row before this bin's tail loads
            nx = base[sArr[(i < OUTN - 1) ? i + 1 : i] * W4];
            switch (n) {
            case 1: break;
            case 2: m = fm4(m, p[W4]); break;
            case 3: m = fm4(m, fm4(p[W4], p[2 * W4])); break;
            case 4: m = fm4(m, fm4(fm4(p[W4], p[2 * W4]), p[3 * W4])); break;
            default: {
                #pragma unroll 2
                for (int y = 1; y < n; y++)
                    m = fm4(m, p[y * W4]);
            } break;
            }
            *(float4*)&rowp[ty][i][tx * 4] = m;
        }
    }
    __syncwarp();   // warp-private rowp: no block barrier needed

    // ---- Phase 2: col-bin maxes for this warp's 2 channels ----
    const int ch0 = ty & ~1;
    float* __restrict__ outg =
        out + ((size_t)r * Cc + cg * CPB + ch0) * (OUTN * OUTN);
    #pragma unroll
    for (int k = 0; k < 4; k++) {
        const int o = lane + k * 32;
        if (o < 98) {
            const int csel = (o >= 49);
            const int b = o - csel * 49;
            const int i = (b * 37) >> 8;   // b/7 for b<=48
            const int j = b - i * OUTN;
            const int s = x1 + (j * Wr) / OUTN;
            const int n = (x1 + ((j + 1) * Wr + OUTN - 1) / OUTN) - s;  // >=1
            const float* __restrict__ rp = &rowp[ch0 + csel][i][s];
            float m;
            switch (n) {
            case 1: m = rp[0]; break;
            case 2: m = fmaxf(rp[0], rp[1]); break;
            case 3: m = fmaxf(fmaxf(rp[0], rp[1]), rp[2]); break;
            case 4: m = fmaxf(fmaxf(rp[0], rp[1]), fmaxf(rp[2], rp[3])); break;
            default: {
                m = rp[0];
                #pragma unroll 2
                for (int x = 1; x < n; x++)
                    m = fmaxf(m, rp[x]);
            } break;
            }
            outg[o] = m;
        }
    }
}

extern "C" void kernel_launch(void* const* d_in, const int* in_sizes, int n_in,
                              void* d_out, int out_size) {
    const float* images  = (const float*)d_in[0];
    const float* rois    = (const float*)d_in[1];
    const int*   roi_idx = (const int*)d_in[2];
    float* out = (float*)d_out;

    dim3 grid(Cc / CPB, Rc);   // (16, 256) = 4096 blocks
    dim3 block(16, 16);        // 256 threads
    roipool_kernel<<<grid, block>>>(images, rois, roi_idx, out);
}

// round 17
// speedup vs baseline: 1.6988x; 1.6988x over previous
#include <cuda_runtime.h>
#include <float.h>

// ROI adaptive max pool 7x7 — R15 inner code (warp-private, barrier-free,
// trip-count-specialized) at finer block granularity: CPB=8, 128-thread
// blocks, 8192 blocks -> ~6.9 waves (halved tail quantum), full 2048
// threads/SM residency.
// images: [8,256,56,56] f32; rois: [256,4] f32; roi_idx: [256] i32
// out: [256,256,7,7] f32

#define Hc 56
#define Wc 56
#define Cc 256
#define Rc 256
#define OUTN 7
#define CPB 8
#define W4 (Wc / 4)   // 14

__device__ __forceinline__ float4 fm4(float4 a, float4 b) {
    return make_float4(fmaxf(a.x, b.x), fmaxf(a.y, b.y),
                       fmaxf(a.z, b.z), fmaxf(a.w, b.w));
}

__global__ __launch_bounds__(128, 16) void roipool_kernel(
    const float* __restrict__ images,
    const float* __restrict__ rois,
    const int* __restrict__ roi_idx,
    float* __restrict__ out)
{
    __shared__ float rowp[CPB][OUTN][60];

    const int r  = blockIdx.y;
    const int cg = blockIdx.x;
    const int tx = threadIdx.x;            // 0..15 quad
    const int ty = threadIdx.y;            // 0..7 channel
    const int lane = (ty & 1) * 16 + tx;   // lane within warp

    const float4 rv = ((const float4*)rois)[r];
    const int x1 = (int)floorf(rv.x * (float)Wc);
    const int y1 = (int)floorf(rv.y * (float)Hc);
    const int x2 = (int)ceilf (rv.z * (float)Wc);
    const int y2 = (int)ceilf (rv.w * (float)Hc);
    const int Hr = y2 - y1;
    const int Wr = x2 - x1;

    const int n_img = roi_idx[r];
    const float* __restrict__ img =
        images + (size_t)(n_img * Cc + cg * CPB + ty) * (Hc * Wc);

    // ---- Phase 1: row-bin maxes (trip-count-specialized switch) ----
    const int qlo = x1 >> 2;
    const int qhi = (x2 + 3) >> 2;
    if (tx >= qlo && tx < qhi) {
        const float4* __restrict__ base = (const float4*)img + tx;
        #pragma unroll
        for (int i = 0; i < OUTN; i++) {
            const int s = y1 + (i * Hr) / OUTN;
            const int n = (y1 + ((i + 1) * Hr + OUTN - 1) / OUTN) - s;  // >=1
            const float4* __restrict__ p = base + s * W4;
            float4 m;
            switch (n) {
            case 1: m = p[0]; break;
            case 2: m = fm4(p[0], p[W4]); break;
            case 3: m = fm4(fm4(p[0], p[W4]), p[2 * W4]); break;
            case 4: m = fm4(fm4(p[0], p[W4]), fm4(p[2 * W4], p[3 * W4])); break;
            default: {
                m = p[0];
                #pragma unroll 2
                for (int y = 1; y < n; y++)
                    m = fm4(m, p[y * W4]);
            } break;
            }
            *(float4*)&rowp[ty][i][tx * 4] = m;
        }
    }
    __syncwarp();   // warp-private rowp: no block barrier needed

    // ---- Phase 2: col-bin maxes for this warp's 2 channels ----
    const int ch0 = ty & ~1;
    float* __restrict__ outg =
        out + ((size_t)r * Cc + cg * CPB + ch0) * (OUTN * OUTN);
    #pragma unroll
    for (int k = 0; k < 4; k++) {
        const int o = lane + k * 32;
        if (o < 98) {
            const int csel = (o >= 49);
            const int b = o - csel * 49;
            const int i = (b * 37) >> 8;   // b/7 for b<=48
            const int j = b - i * OUTN;
            const int s = x1 + (j * Wr) / OUTN;
            const int n = (x1 + ((j + 1) * Wr + OUTN - 1) / OUTN) - s;  // >=1
            const float* __restrict__ rp = &rowp[ch0 + csel][i][s];
            float m;
            switch (n) {
            case 1: m = rp[0]; break;
            case 2: m = fmaxf(rp[0], rp[1]); break;
            case 3: m = fmaxf(fmaxf(rp[0], rp[1]), rp[2]); break;
            case 4: m = fmaxf(fmaxf(rp[0], rp[1]), fmaxf(rp[2], rp[3])); break;
            default: {
                m = rp[0];
                #pragma unroll 2
                for (int x = 1; x < n; x++)
                    m = fmaxf(m, rp[x]);
            } break;
            }
            outg[o] = m;
        }
    }
}

extern "C" void kernel_launch(void* const* d_in, const int* in_sizes, int n_in,
                              void* d_out, int out_size) {
    const float* images  = (const float*)d_in[0];
    const float* rois    = (const float*)d_in[1];
    const int*   roi_idx = (const int*)d_in[2];
    float* out = (float*)d_out;

    dim3 grid(Cc / CPB, Rc);   // (32, 256) = 8192 blocks
    dim3 block(16, CPB);       // 128 threads
    roipool_kernel<<<grid, block>>>(images, rois, roi_idx, out);
}